// round 14
// baseline (speedup 1.0000x reference)
#include <cuda_runtime.h>
#include <cuda_bf16.h>
#include <cuda_fp16.h>
#include <cstdint>
#include <math.h>

#define B_  4
#define T_  2048
#define C_  1024
#define NH_ 16
#define HD_ 64
#define M_  (B_*T_)          // 8192 tokens
#define PQ_ 72               // padded row length (144B) for q/k prepack

// ---------------- scratch (static device globals; no runtime alloc) --------
__device__ __align__(256) __half  g_xf  [(size_t)M_ * C_];
__device__ __align__(256) __half  g_wtf [(size_t)3 * C_ * C_];   // W_attn^T fp16 [3C, C]
__device__ __align__(256) __half  g_wptf[(size_t)C_ * C_];       // W_proj^T fp16 [C, C]
__device__ __align__(256) __half  g_yf  [(size_t)M_ * C_];       // attn out fp16
__device__ __align__(256) __half  g_qpf [(size_t)B_*NH_*T_*PQ_];
__device__ __align__(256) __half  g_kpf [(size_t)B_*NH_*T_*PQ_];
__device__ __align__(256) __half  g_vtf [(size_t)B_*NH_*HD_*T_];

// ---------------- helpers ---------------------------------------------------
__device__ __forceinline__ uint32_t smem_u32(const void* p) {
    uint32_t a;
    asm("{ .reg .u64 t; cvta.to.shared.u64 t, %1; cvt.u32.u64 %0, t; }" : "=r"(a) : "l"(p));
    return a;
}

#define LDSM_X4(r0, r1, r2, r3, addr) \
    asm volatile("ldmatrix.sync.aligned.m8n8.x4.shared.b16 {%0,%1,%2,%3}, [%4];" \
        : "=r"(r0), "=r"(r1), "=r"(r2), "=r"(r3) : "r"(addr))

#define CP_ASYNC16(dst, src) \
    asm volatile("cp.async.cg.shared.global [%0], [%1], 16;" :: "r"(dst), "l"(src))
#define CP_COMMIT() asm volatile("cp.async.commit_group;" ::: "memory")
#define CP_WAIT(n)  asm volatile("cp.async.wait_group %0;" :: "n"(n) : "memory")

// fp16 MMA
__device__ __forceinline__ void mma16816h(float* d, const uint32_t* a,
                                          uint32_t b0, uint32_t b1) {
    asm("mma.sync.aligned.m16n8k16.row.col.f32.f16.f16.f32 "
        "{%0,%1,%2,%3}, {%4,%5,%6,%7}, {%8,%9}, {%0,%1,%2,%3};"
        : "+f"(d[0]), "+f"(d[1]), "+f"(d[2]), "+f"(d[3])
        : "r"(a[0]), "r"(a[1]), "r"(a[2]), "r"(a[3]), "r"(b0), "r"(b1));
}

__device__ __forceinline__ uint32_t pack_f16(float a, float b) {
    uint32_t r;
    asm("cvt.rn.f16x2.f32 %0, %1, %2;" : "=r"(r) : "f"(b), "f"(a));  // lo16 = a
    return r;
}

__device__ __forceinline__ float ex2f(float x) {
    float r; asm("ex2.approx.f32 %0, %1;" : "=f"(r) : "f"(x)); return r;
}

// ---------------- merged conversion kernel -----------------------------------
// blocks [0, XB)            : x fp32 -> fp16           (1024 elems/block)
// blocks [XB, XB+96*32)     : W_attn^T transpose+cvt   (32x32 tile each)
// blocks [XB+96*32, +32*32) : W_proj^T transpose+cvt
#define XB (M_ * C_ / 1024)

__global__ __launch_bounds__(256)
void convert_all(const float* __restrict__ x, const float* __restrict__ Wa,
                 const float* __restrict__ Wp,
                 __half* __restrict__ xf, __half* __restrict__ wtf,
                 __half* __restrict__ wptf)
{
    __shared__ float t[32][33];
    const int bid = blockIdx.x;
    if (bid < XB) {
        int i = (bid * 256 + threadIdx.x) * 4;
        float4 v = *(const float4*)(x + i);
        *(uint2*)(xf + i) = make_uint2(pack_f16(v.x, v.y), pack_f16(v.z, v.w));
        return;
    }
    const float* W; __half* Tf; int K, N, tb;
    if (bid < XB + 96 * 32) { W = Wa; Tf = wtf;  K = C_; N = 3 * C_; tb = bid - XB; }
    else                    { W = Wp; Tf = wptf; K = C_; N = C_;     tb = bid - XB - 96 * 32; }
    const int nblk = N / 32;
    int n0 = (tb % nblk) * 32, k0 = (tb / nblk) * 32;
    int tx = threadIdx.x & 31, ty = threadIdx.x >> 5;
    #pragma unroll
    for (int i = 0; i < 32; i += 8)
        t[ty + i][tx] = W[(size_t)(k0 + ty + i) * N + n0 + tx];
    __syncthreads();
    #pragma unroll
    for (int i = 0; i < 32; i += 8)
        Tf[(size_t)(n0 + ty + i) * K + k0 + tx] = __float2half_rn(t[tx][ty + i]);
}

// ---------------- single-term fp16 pipelined GEMM ---------------------------
// C[M,N] = A[M,K] @ B[N,K]^T + bias.  K-chunk 64, 2-stage cp.async.
// MODE 0: fp32 C (proj).
// MODE 1: qkv — q/k cols fused fp16 prepack; v cols transposed fp16 [bh,d,T].
#define GSTR 144                    // 64 halves (128B) + 16B pad
#define GSTG (2 * 128 * GSTR)       // 36864: A + B arrays
#define SM_A  0
#define SM_B  (128 * GSTR)          // 18432
#define SM_BIAS (2 * GSTG)          // 73728
#define GEMM_SMEM (2 * GSTG + 512)

template<int MODE>
__global__ __launch_bounds__(256, 2)
void gemm_mma_kernel(const __half* __restrict__ Af, const __half* __restrict__ Bf,
                     const float* __restrict__ bias, float* __restrict__ Cout,
                     __half* __restrict__ qf, __half* __restrict__ kfp,
                     __half* __restrict__ vf,
                     int M, int N, int K)
{
    extern __shared__ __align__(16) char sm[];
    float* sbias = (float*)(sm + SM_BIAS);
    const uint32_t smb = smem_u32(sm);

    const int tid  = threadIdx.x;
    const int wid  = tid >> 5;
    const int lane = tid & 31;
    const int mw   = wid & 3;
    const int nw   = wid >> 2;
    const int row0 = blockIdx.y * 128;
    const int col0 = blockIdx.x * 128;

    if (tid < 128) sbias[tid] = bias[col0 + tid];

    float acc[2][8][4];
    #pragma unroll
    for (int i = 0; i < 2; i++)
        #pragma unroll
        for (int j = 0; j < 8; j++)
            #pragma unroll
            for (int q = 0; q < 4; q++) acc[i][j][q] = 0.f;

    const int lrow = tid >> 1;          // 0..127
    const int lg0  = (tid & 1) * 4;     // granule base (4 granules of 16B each)
    const int lr = lane & 15;
    const int lc = lane >> 4;
    const int NC = K >> 6;              // k-chunks of 64

    auto load_stage = [&](int kc, int stg) {
        const uint32_t sb = smb + stg * GSTG;
        const uint32_t so = (uint32_t)(lrow * GSTR + lg0 * 16);
        const size_t ga = (size_t)(row0 + lrow) * K + (kc << 6) + lg0 * 8;
        const size_t gb = (size_t)(col0 + lrow) * K + (kc << 6) + lg0 * 8;
        #pragma unroll
        for (int g = 0; g < 4; g++) {
            CP_ASYNC16(sb + SM_A + so + g * 16, (const char*)(Af + ga + g * 8));
            CP_ASYNC16(sb + SM_B + so + g * 16, (const char*)(Bf + gb + g * 8));
        }
        CP_COMMIT();
    };

    load_stage(0, 0);

    for (int kc = 0; kc < NC; kc++) {
        const int stg = kc & 1;
        if (kc + 1 < NC) {
            load_stage(kc + 1, stg ^ 1);
            CP_WAIT(1);
        } else {
            CP_WAIT(0);
        }
        __syncthreads();

        const uint32_t sb = smb + stg * GSTG;
        #pragma unroll
        for (int ks = 0; ks < 4; ks++) {
            const uint32_t kb = (uint32_t)(lc * 16 + ks * 32);

            uint32_t af[2][4];
            #pragma unroll
            for (int mf = 0; mf < 2; mf++) {
                uint32_t ao = sb + SM_A + (uint32_t)((mw * 32 + mf * 16 + lr) * GSTR) + kb;
                LDSM_X4(af[mf][0], af[mf][1], af[mf][2], af[mf][3], ao);
            }

            #pragma unroll
            for (int np = 0; np < 4; np++) {
                uint32_t bo = sb + SM_B + (uint32_t)((nw * 64 + np * 16 + lr) * GSTR) + kb;
                uint32_t b0, b1, b2, b3;
                LDSM_X4(b0, b1, b2, b3, bo);
                mma16816h(acc[0][np * 2 + 0], af[0], b0, b2);
                mma16816h(acc[0][np * 2 + 1], af[0], b1, b3);
                mma16816h(acc[1][np * 2 + 0], af[1], b0, b2);
                mma16816h(acc[1][np * 2 + 1], af[1], b1, b3);
            }
        }
        __syncthreads();
    }

    if (MODE == 1) {
        if (col0 < 2 * C_) {
            // fused q/k prepack epilogue: fp16, q pre-scaled by 0.125*log2(e)
            const bool isk = (col0 >= C_);
            const float sc = isk ? 1.0f : 0.125f * 1.44269504089f;
            __half* dst = isk ? kfp : qf;
            const int h0 = (col0 & (C_ - 1)) >> 6;
            #pragma unroll
            for (int mf = 0; mf < 2; mf++) {
                int r_ = row0 + mw * 32 + mf * 16 + (lane >> 2);
                int bi = r_ >> 11, ti = r_ & (T_ - 1);
                #pragma unroll
                for (int nf = 0; nf < 8; nf++) {
                    int cl = nw * 64 + nf * 8 + (lane & 3) * 2;
                    int head = h0 + (cl >> 6), d = cl & 63;
                    float bb0 = sbias[cl], bb1 = sbias[cl + 1];
                    size_t base = ((size_t)(bi * NH_ + head) * T_ + ti) * PQ_ + d;
                    *(uint32_t*)(dst + base) =
                        pack_f16((acc[mf][nf][0] + bb0) * sc, (acc[mf][nf][1] + bb1) * sc);
                    *(uint32_t*)(dst + base + 8 * PQ_) =
                        pack_f16((acc[mf][nf][2] + bb0) * sc, (acc[mf][nf][3] + bb1) * sc);
                }
            }
        } else {
            // fused v epilogue: write transposed fp16 [bh, d, T]
            const int h0 = (col0 - 2 * C_) >> 6;
            #pragma unroll
            for (int mf = 0; mf < 2; mf++) {
                int r_ = row0 + mw * 32 + mf * 16 + (lane >> 2);
                int bi = r_ >> 11, ti = r_ & (T_ - 1);
                #pragma unroll
                for (int nf = 0; nf < 8; nf++) {
                    int cl = nw * 64 + nf * 8 + (lane & 3) * 2;
                    int head = h0 + (cl >> 6), d = cl & 63;
                    float bb0 = sbias[cl], bb1 = sbias[cl + 1];
                    size_t base = ((size_t)(bi * NH_ + head) * HD_ + d) * T_ + ti;
                    vf[base]          = __float2half_rn(acc[mf][nf][0] + bb0);
                    vf[base + T_]     = __float2half_rn(acc[mf][nf][1] + bb1);
                    vf[base + 8]      = __float2half_rn(acc[mf][nf][2] + bb0);
                    vf[base + T_ + 8] = __float2half_rn(acc[mf][nf][3] + bb1);
                }
            }
        }
    } else {
        #pragma unroll
        for (int mf = 0; mf < 2; mf++) {
            int r_ = row0 + mw * 32 + mf * 16 + (lane >> 2);
            #pragma unroll
            for (int nf = 0; nf < 8; nf++) {
                int cl = nw * 64 + nf * 8 + (lane & 3) * 2;
                float b0 = sbias[cl], b1 = sbias[cl + 1];
                float2 v0 = {acc[mf][nf][0] + b0, acc[mf][nf][1] + b1};
                float2 v1 = {acc[mf][nf][2] + b0, acc[mf][nf][3] + b1};
                *(float2*)(Cout + (size_t)r_ * N + col0 + cl) = v0;
                *(float2*)(Cout + (size_t)(r_ + 8) * N + col0 + cl) = v1;
            }
        }
    }
}

// ---------------- fp16 flash attention, 3-stage cp.async pipeline -----------
#define AT_STR 144
#define SQ_F 0
#define AST_BASE 18432
#define AST_SIZE 18432
#define AST_K 0
#define AST_V 9216
#define ATTN_SMEM (AST_BASE + 3 * AST_SIZE)   // 73728

__global__ __launch_bounds__(256, 2)
void attn_mma_kernel(const __half* __restrict__ qf, const __half* __restrict__ kf,
                     const __half* __restrict__ vf, __half* __restrict__ yf)
{
    extern __shared__ char sm[];
    const uint32_t smb = smem_u32(sm);
    const int tid = threadIdx.x, lane = tid & 31, wid = tid >> 5;
    const int qb = (int)(gridDim.x - 1 - blockIdx.x);
    const int h  = blockIdx.y, b = blockIdx.z;
    const int bh = b * NH_ + h;

    // Q tile (group 0)
    {
        const int row = tid >> 1, g0 = (tid & 1) * 4;
        const size_t gbase = ((size_t)bh * T_ + qb * 128 + row) * PQ_ + g0 * 8;
        const uint32_t sbase = smb + SQ_F + (uint32_t)(row * AT_STR) + g0 * 16;
        #pragma unroll
        for (int g = 0; g < 4; g++)
            CP_ASYNC16(sbase + g * 16, (const char*)(qf + gbase + g * 8));
        CP_COMMIT();
    }

    const int srow = tid >> 2;
    const int sg   = (tid & 3) * 2;

    auto load_stage = [&](int kt, int stg) {
        const uint32_t sb = smb + AST_BASE + stg * AST_SIZE;
        const uint32_t so = (uint32_t)(srow * AT_STR + sg * 16);
        const size_t gk = ((size_t)bh * T_ + kt * 64 + srow) * PQ_ + sg * 8;
        const size_t gv = ((size_t)bh * HD_ + srow) * T_ + kt * 64 + sg * 8;
        CP_ASYNC16(sb + AST_K + so,      (const char*)(kf + gk));
        CP_ASYNC16(sb + AST_K + so + 16, (const char*)(kf + gk + 8));
        CP_ASYNC16(sb + AST_V + so,      (const char*)(vf + gv));
        CP_ASYNC16(sb + AST_V + so + 16, (const char*)(vf + gv + 8));
        CP_COMMIT();
    };

    float m0 = -1e30f, m1 = -1e30f, lsum0 = 0.f, lsum1 = 0.f;
    float o[8][4];
    #pragma unroll
    for (int j = 0; j < 8; j++)
        #pragma unroll
        for (int q = 0; q < 4; q++) o[j][q] = 0.f;

    const int lr = lane & 15, lc = lane >> 4;
    const int rowg0 = qb * 128 + wid * 16 + (lane >> 2);
    const int ntiles = 2 * qb + 2;

    load_stage(0, 0);
    load_stage(1, 1);      // ntiles >= 2 always

    int stg = 0;
    for (int kt = 0; kt < ntiles; kt++) {
        if (kt + 2 < ntiles) {
            int ns = stg + 2; if (ns >= 3) ns -= 3;
            load_stage(kt + 2, ns);
            CP_WAIT(2);
        } else if (kt + 1 < ntiles) {
            CP_WAIT(1);
        } else {
            CP_WAIT(0);
        }
        __syncthreads();

        const uint32_t sb = smb + AST_BASE + stg * AST_SIZE;

        float s[8][4];
        #pragma unroll
        for (int j = 0; j < 8; j++)
            #pragma unroll
            for (int q = 0; q < 4; q++) s[j][q] = 0.f;

        #pragma unroll
        for (int ks = 0; ks < 4; ks++) {
            const uint32_t kb = (uint32_t)(lc * 16 + ks * 32);
            uint32_t aq[4];
            uint32_t ao = smb + SQ_F + (uint32_t)((wid * 16 + lr) * AT_STR) + kb;
            LDSM_X4(aq[0], aq[1], aq[2], aq[3], ao);
            #pragma unroll
            for (int np = 0; np < 4; np++) {
                uint32_t bo = sb + AST_K + (uint32_t)((np * 16 + lr) * AT_STR) + kb;
                uint32_t b0, b1, b2, b3;
                LDSM_X4(b0, b1, b2, b3, bo);
                mma16816h(s[np * 2 + 0], aq, b0, b2);
                mma16816h(s[np * 2 + 1], aq, b1, b3);
            }
        }

        if (kt >= 2 * qb) {
            const int colb = kt * 64 + 2 * (lane & 3);
            #pragma unroll
            for (int j = 0; j < 8; j++) {
                int c0 = colb + 8 * j;
                if (c0     > rowg0)     s[j][0] = -1e30f;
                if (c0 + 1 > rowg0)     s[j][1] = -1e30f;
                if (c0     > rowg0 + 8) s[j][2] = -1e30f;
                if (c0 + 1 > rowg0 + 8) s[j][3] = -1e30f;
            }
        }

        float mx0 = -1e30f, mx1 = -1e30f;
        #pragma unroll
        for (int j = 0; j < 8; j++) {
            mx0 = fmaxf(mx0, fmaxf(s[j][0], s[j][1]));
            mx1 = fmaxf(mx1, fmaxf(s[j][2], s[j][3]));
        }
        mx0 = fmaxf(mx0, __shfl_xor_sync(0xffffffffu, mx0, 1));
        mx0 = fmaxf(mx0, __shfl_xor_sync(0xffffffffu, mx0, 2));
        mx1 = fmaxf(mx1, __shfl_xor_sync(0xffffffffu, mx1, 1));
        mx1 = fmaxf(mx1, __shfl_xor_sync(0xffffffffu, mx1, 2));

        float mn0 = fmaxf(m0, mx0), mn1 = fmaxf(m1, mx1);
        float a0 = ex2f(m0 - mn0),  a1 = ex2f(m1 - mn1);
        m0 = mn0; m1 = mn1;

        float sum0 = 0.f, sum1 = 0.f;
        #pragma unroll
        for (int j = 0; j < 8; j++) {
            s[j][0] = ex2f(s[j][0] - mn0);
            s[j][1] = ex2f(s[j][1] - mn0);
            s[j][2] = ex2f(s[j][2] - mn1);
            s[j][3] = ex2f(s[j][3] - mn1);
            sum0 += s[j][0] + s[j][1];
            sum1 += s[j][2] + s[j][3];
        }
        sum0 += __shfl_xor_sync(0xffffffffu, sum0, 1);
        sum0 += __shfl_xor_sync(0xffffffffu, sum0, 2);
        sum1 += __shfl_xor_sync(0xffffffffu, sum1, 1);
        sum1 += __shfl_xor_sync(0xffffffffu, sum1, 2);
        lsum0 = lsum0 * a0 + sum0;
        lsum1 = lsum1 * a1 + sum1;

        #pragma unroll
        for (int j = 0; j < 8; j++) {
            o[j][0] *= a0; o[j][1] *= a0;
            o[j][2] *= a1; o[j][3] *= a1;
        }

        uint32_t pf[4][4];
        #pragma unroll
        for (int s2 = 0; s2 < 4; s2++) {
            pf[s2][0] = pack_f16(s[2*s2  ][0], s[2*s2  ][1]);
            pf[s2][1] = pack_f16(s[2*s2  ][2], s[2*s2  ][3]);
            pf[s2][2] = pack_f16(s[2*s2+1][0], s[2*s2+1][1]);
            pf[s2][3] = pack_f16(s[2*s2+1][2], s[2*s2+1][3]);
        }

        #pragma unroll
        for (int s2 = 0; s2 < 4; s2++) {
            const uint32_t kb = (uint32_t)(lc * 16 + s2 * 32);
            #pragma unroll
            for (int np = 0; np < 4; np++) {
                uint32_t bo = sb + AST_V + (uint32_t)((np * 16 + lr) * AT_STR) + kb;
                uint32_t b0, b1, b2, b3;
                LDSM_X4(b0, b1, b2, b3, bo);
                mma16816h(o[np * 2 + 0], pf[s2], b0, b2);
                mma16816h(o[np * 2 + 1], pf[s2], b1, b3);
            }
        }
        __syncthreads();
        if (++stg == 3) stg = 0;
    }

    float inv0 = 1.f / lsum0, inv1 = 1.f / lsum1;
    const int tok0 = b * T_ + qb * 128 + wid * 16 + (lane >> 2);
    #pragma unroll
    for (int nf = 0; nf < 8; nf++) {
        int d = h * HD_ + nf * 8 + (lane & 3) * 2;
        *(uint32_t*)(yf + (size_t)tok0 * C_ + d)       = pack_f16(o[nf][0] * inv0, o[nf][1] * inv0);
        *(uint32_t*)(yf + (size_t)(tok0 + 8) * C_ + d) = pack_f16(o[nf][2] * inv1, o[nf][3] * inv1);
    }
}

// ---------------------------------------------------------------------------
extern "C" void kernel_launch(void* const* d_in, const int* in_sizes, int n_in,
                              void* d_out, int out_size)
{
    const float* x      = (const float*)d_in[0];
    const float* W_attn = (const float*)d_in[1];
    const float* b_attn = (const float*)d_in[2];
    const float* W_proj = (const float*)d_in[3];
    const float* b_proj = (const float*)d_in[4];
    float* out = (float*)d_out;

    __half *xf, *wtf, *wptf, *yf, *qpf, *kpf, *vtf;
    cudaGetSymbolAddress((void**)&xf,   g_xf);
    cudaGetSymbolAddress((void**)&wtf,  g_wtf);
    cudaGetSymbolAddress((void**)&wptf, g_wptf);
    cudaGetSymbolAddress((void**)&yf,   g_yf);
    cudaGetSymbolAddress((void**)&qpf,  g_qpf);
    cudaGetSymbolAddress((void**)&kpf,  g_kpf);
    cudaGetSymbolAddress((void**)&vtf,  g_vtf);

    cudaFuncSetAttribute(gemm_mma_kernel<0>,
                         cudaFuncAttributeMaxDynamicSharedMemorySize, GEMM_SMEM);
    cudaFuncSetAttribute(gemm_mma_kernel<1>,
                         cudaFuncAttributeMaxDynamicSharedMemorySize, GEMM_SMEM);
    cudaFuncSetAttribute(attn_mma_kernel,
                         cudaFuncAttributeMaxDynamicSharedMemorySize, ATTN_SMEM);

    // 1) all conversions in one launch
    convert_all<<<XB + 96 * 32 + 32 * 32, 256>>>(x, W_attn, W_proj, xf, wtf, wptf);

    // 2) qkv GEMM (k-chunk 64) with fully fused epilogue
    gemm_mma_kernel<1><<<dim3(3 * C_ / 128, M_ / 128), 256, GEMM_SMEM>>>(
        xf, wtf, b_attn, nullptr, qpf, kpf, vtf, M_, 3 * C_, C_);

    // 3) fp16 flash attention (3-stage) -> yf
    attn_mma_kernel<<<dim3(T_ / 128, NH_, B_), 256, ATTN_SMEM>>>(qpf, kpf, vtf, yf);

    // 4) out = y @ W_proj + b_proj
    gemm_mma_kernel<0><<<dim3(C_ / 128, M_ / 128), 256, GEMM_SMEM>>>(
        yf, wptf, b_proj, out, nullptr, nullptr, nullptr, M_, C_, C_);
}

// round 15
// speedup vs baseline: 1.1282x; 1.1282x over previous
#include <cuda_runtime.h>
#include <cuda_bf16.h>
#include <cuda_fp16.h>
#include <cstdint>
#include <math.h>

#define B_  4
#define T_  2048
#define C_  1024
#define NH_ 16
#define HD_ 64
#define M_  (B_*T_)          // 8192 tokens
#define PQ_ 72               // padded row length (144B) for q/k prepack

// ---------------- scratch (static device globals; no runtime alloc) --------
__device__ __align__(256) __half  g_xf  [(size_t)M_ * C_];
__device__ __align__(256) __half  g_wtf [(size_t)3 * C_ * C_];   // W_attn^T fp16 [3C, C]
__device__ __align__(256) __half  g_wptf[(size_t)C_ * C_];       // W_proj^T fp16 [C, C]
__device__ __align__(256) __half  g_yf  [(size_t)M_ * C_];       // attn out fp16
__device__ __align__(256) __half  g_qpf [(size_t)B_*NH_*T_*PQ_];
__device__ __align__(256) __half  g_kpf [(size_t)B_*NH_*T_*PQ_];
__device__ __align__(256) __half  g_vtf [(size_t)B_*NH_*HD_*T_];

// ---------------- helpers ---------------------------------------------------
__device__ __forceinline__ uint32_t smem_u32(const void* p) {
    uint32_t a;
    asm("{ .reg .u64 t; cvta.to.shared.u64 t, %1; cvt.u32.u64 %0, t; }" : "=r"(a) : "l"(p));
    return a;
}

#define LDSM_X4(r0, r1, r2, r3, addr) \
    asm volatile("ldmatrix.sync.aligned.m8n8.x4.shared.b16 {%0,%1,%2,%3}, [%4];" \
        : "=r"(r0), "=r"(r1), "=r"(r2), "=r"(r3) : "r"(addr))

#define CP_ASYNC16(dst, src) \
    asm volatile("cp.async.cg.shared.global [%0], [%1], 16;" :: "r"(dst), "l"(src))
#define CP_COMMIT() asm volatile("cp.async.commit_group;" ::: "memory")
#define CP_WAIT(n)  asm volatile("cp.async.wait_group %0;" :: "n"(n) : "memory")

// fp16 MMA
__device__ __forceinline__ void mma16816h(float* d, const uint32_t* a,
                                          uint32_t b0, uint32_t b1) {
    asm("mma.sync.aligned.m16n8k16.row.col.f32.f16.f16.f32 "
        "{%0,%1,%2,%3}, {%4,%5,%6,%7}, {%8,%9}, {%0,%1,%2,%3};"
        : "+f"(d[0]), "+f"(d[1]), "+f"(d[2]), "+f"(d[3])
        : "r"(a[0]), "r"(a[1]), "r"(a[2]), "r"(a[3]), "r"(b0), "r"(b1));
}

__device__ __forceinline__ uint32_t pack_f16(float a, float b) {
    uint32_t r;
    asm("cvt.rn.f16x2.f32 %0, %1, %2;" : "=r"(r) : "f"(b), "f"(a));  // lo16 = a
    return r;
}

__device__ __forceinline__ float ex2f(float x) {
    float r; asm("ex2.approx.f32 %0, %1;" : "=f"(r) : "f"(x)); return r;
}

// ---------------- merged conversion kernel -----------------------------------
// blocks [0, XB)            : x fp32 -> fp16           (1024 elems/block)
// blocks [XB, XB+96*32)     : W_attn^T transpose+cvt   (32x32 tile each)
// blocks [XB+96*32, +32*32) : W_proj^T transpose+cvt
#define XB (M_ * C_ / 1024)

__global__ __launch_bounds__(256)
void convert_all(const float* __restrict__ x, const float* __restrict__ Wa,
                 const float* __restrict__ Wp,
                 __half* __restrict__ xf, __half* __restrict__ wtf,
                 __half* __restrict__ wptf)
{
    __shared__ float t[32][33];
    const int bid = blockIdx.x;
    if (bid < XB) {
        int i = (bid * 256 + threadIdx.x) * 4;
        float4 v = *(const float4*)(x + i);
        *(uint2*)(xf + i) = make_uint2(pack_f16(v.x, v.y), pack_f16(v.z, v.w));
        return;
    }
    const float* W; __half* Tf; int K, N, tb;
    if (bid < XB + 96 * 32) { W = Wa; Tf = wtf;  K = C_; N = 3 * C_; tb = bid - XB; }
    else                    { W = Wp; Tf = wptf; K = C_; N = C_;     tb = bid - XB - 96 * 32; }
    const int nblk = N / 32;
    int n0 = (tb % nblk) * 32, k0 = (tb / nblk) * 32;
    int tx = threadIdx.x & 31, ty = threadIdx.x >> 5;
    #pragma unroll
    for (int i = 0; i < 32; i += 8)
        t[ty + i][tx] = W[(size_t)(k0 + ty + i) * N + n0 + tx];
    __syncthreads();
    #pragma unroll
    for (int i = 0; i < 32; i += 8)
        Tf[(size_t)(n0 + ty + i) * K + k0 + tx] = __float2half_rn(t[tx][ty + i]);
}

// ---------------- single-term fp16 pipelined GEMM (R13-exact) ---------------
// C[M,N] = A[M,K] @ B[N,K]^T + bias.  K-chunk 32, 2-stage cp.async, ASTR 80.
// MODE 0: fp32 C (proj).
// MODE 1: qkv — q/k cols fused fp16 prepack; v cols transposed fp16 [bh,d,T].
#define ASTR 80
#define GSTG 20480                 // 2 arrays x 128 x 80
#define SM_A  0
#define SM_B  10240
#define SM_BIAS (2 * GSTG)         // 40960
#define GEMM_SMEM (2 * GSTG + 512)

template<int MODE>
__global__ __launch_bounds__(256, 2)
void gemm_mma_kernel(const __half* __restrict__ Af, const __half* __restrict__ Bf,
                     const float* __restrict__ bias, float* __restrict__ Cout,
                     __half* __restrict__ qf, __half* __restrict__ kfp,
                     __half* __restrict__ vf,
                     int M, int N, int K)
{
    extern __shared__ __align__(16) char sm[];
    float* sbias = (float*)(sm + SM_BIAS);
    const uint32_t smb = smem_u32(sm);

    const int tid  = threadIdx.x;
    const int wid  = tid >> 5;
    const int lane = tid & 31;
    const int mw   = wid & 3;
    const int nw   = wid >> 2;
    const int row0 = blockIdx.y * 128;
    const int col0 = blockIdx.x * 128;

    if (tid < 128) sbias[tid] = bias[col0 + tid];

    float acc[2][8][4];
    #pragma unroll
    for (int i = 0; i < 2; i++)
        #pragma unroll
        for (int j = 0; j < 8; j++)
            #pragma unroll
            for (int q = 0; q < 4; q++) acc[i][j][q] = 0.f;

    const int sr0 = tid >> 2;          // 0..63
    const int ssg = tid & 3;           // 16B granule
    const int lr = lane & 15;
    const int lc = lane >> 4;
    const int NC = K >> 5;

    auto load_stage = [&](int kc, int stg) {
        const uint32_t sb = smb + stg * GSTG;
        #pragma unroll
        for (int it = 0; it < 2; it++) {
            int r = sr0 + it * 64;
            uint32_t so = (uint32_t)(r * ASTR + ssg * 16);
            size_t ga = (size_t)(row0 + r) * K + (kc << 5) + ssg * 8;
            size_t gb = (size_t)(col0 + r) * K + (kc << 5) + ssg * 8;
            CP_ASYNC16(sb + SM_A + so, (const char*)(Af + ga));
            CP_ASYNC16(sb + SM_B + so, (const char*)(Bf + gb));
        }
        CP_COMMIT();
    };

    load_stage(0, 0);

    for (int kc = 0; kc < NC; kc++) {
        const int stg = kc & 1;
        if (kc + 1 < NC) {
            load_stage(kc + 1, stg ^ 1);
            CP_WAIT(1);
        } else {
            CP_WAIT(0);
        }
        __syncthreads();

        const uint32_t sb = smb + stg * GSTG;
        #pragma unroll
        for (int ks = 0; ks < 2; ks++) {
            const uint32_t kb = (uint32_t)(lc * 16 + ks * 32);

            uint32_t af[2][4];
            #pragma unroll
            for (int mf = 0; mf < 2; mf++) {
                uint32_t ao = sb + SM_A + (uint32_t)((mw * 32 + mf * 16 + lr) * ASTR) + kb;
                LDSM_X4(af[mf][0], af[mf][1], af[mf][2], af[mf][3], ao);
            }

            #pragma unroll
            for (int np = 0; np < 4; np++) {
                uint32_t bo = sb + SM_B + (uint32_t)((nw * 64 + np * 16 + lr) * ASTR) + kb;
                uint32_t b0, b1, b2, b3;
                LDSM_X4(b0, b1, b2, b3, bo);
                mma16816h(acc[0][np * 2 + 0], af[0], b0, b2);
                mma16816h(acc[0][np * 2 + 1], af[0], b1, b3);
                mma16816h(acc[1][np * 2 + 0], af[1], b0, b2);
                mma16816h(acc[1][np * 2 + 1], af[1], b1, b3);
            }
        }
        __syncthreads();
    }

    if (MODE == 1) {
        if (col0 < 2 * C_) {
            // fused q/k prepack epilogue: fp16, q pre-scaled by 0.125*log2(e)
            const bool isk = (col0 >= C_);
            const float sc = isk ? 1.0f : 0.125f * 1.44269504089f;
            __half* dst = isk ? kfp : qf;
            const int h0 = (col0 & (C_ - 1)) >> 6;
            #pragma unroll
            for (int mf = 0; mf < 2; mf++) {
                int r_ = row0 + mw * 32 + mf * 16 + (lane >> 2);
                int bi = r_ >> 11, ti = r_ & (T_ - 1);
                #pragma unroll
                for (int nf = 0; nf < 8; nf++) {
                    int cl = nw * 64 + nf * 8 + (lane & 3) * 2;
                    int head = h0 + (cl >> 6), d = cl & 63;
                    float bb0 = sbias[cl], bb1 = sbias[cl + 1];
                    size_t base = ((size_t)(bi * NH_ + head) * T_ + ti) * PQ_ + d;
                    *(uint32_t*)(dst + base) =
                        pack_f16((acc[mf][nf][0] + bb0) * sc, (acc[mf][nf][1] + bb1) * sc);
                    *(uint32_t*)(dst + base + 8 * PQ_) =
                        pack_f16((acc[mf][nf][2] + bb0) * sc, (acc[mf][nf][3] + bb1) * sc);
                }
            }
        } else {
            // fused v epilogue: write transposed fp16 [bh, d, T]
            const int h0 = (col0 - 2 * C_) >> 6;
            #pragma unroll
            for (int mf = 0; mf < 2; mf++) {
                int r_ = row0 + mw * 32 + mf * 16 + (lane >> 2);
                int bi = r_ >> 11, ti = r_ & (T_ - 1);
                #pragma unroll
                for (int nf = 0; nf < 8; nf++) {
                    int cl = nw * 64 + nf * 8 + (lane & 3) * 2;
                    int head = h0 + (cl >> 6), d = cl & 63;
                    float bb0 = sbias[cl], bb1 = sbias[cl + 1];
                    size_t base = ((size_t)(bi * NH_ + head) * HD_ + d) * T_ + ti;
                    vf[base]          = __float2half_rn(acc[mf][nf][0] + bb0);
                    vf[base + T_]     = __float2half_rn(acc[mf][nf][1] + bb1);
                    vf[base + 8]      = __float2half_rn(acc[mf][nf][2] + bb0);
                    vf[base + T_ + 8] = __float2half_rn(acc[mf][nf][3] + bb1);
                }
            }
        }
    } else {
        #pragma unroll
        for (int mf = 0; mf < 2; mf++) {
            int r_ = row0 + mw * 32 + mf * 16 + (lane >> 2);
            #pragma unroll
            for (int nf = 0; nf < 8; nf++) {
                int cl = nw * 64 + nf * 8 + (lane & 3) * 2;
                float b0 = sbias[cl], b1 = sbias[cl + 1];
                float2 v0 = {acc[mf][nf][0] + b0, acc[mf][nf][1] + b1};
                float2 v1 = {acc[mf][nf][2] + b0, acc[mf][nf][3] + b1};
                *(float2*)(Cout + (size_t)r_ * N + col0 + cl) = v0;
                *(float2*)(Cout + (size_t)(r_ + 8) * N + col0 + cl) = v1;
            }
        }
    }
}

// ---------------- fp16 flash attention, 3-stage cp.async pipeline -----------
#define AT_STR 144
#define SQ_F 0
#define AST_BASE 18432
#define AST_SIZE 18432
#define AST_K 0
#define AST_V 9216
#define ATTN_SMEM (AST_BASE + 3 * AST_SIZE)   // 73728

__global__ __launch_bounds__(256, 2)
void attn_mma_kernel(const __half* __restrict__ qf, const __half* __restrict__ kf,
                     const __half* __restrict__ vf, __half* __restrict__ yf)
{
    extern __shared__ char sm[];
    const uint32_t smb = smem_u32(sm);
    const int tid = threadIdx.x, lane = tid & 31, wid = tid >> 5;
    const int qb = (int)(gridDim.x - 1 - blockIdx.x);
    const int h  = blockIdx.y, b = blockIdx.z;
    const int bh = b * NH_ + h;

    // Q tile (group 0)
    {
        const int row = tid >> 1, g0 = (tid & 1) * 4;
        const size_t gbase = ((size_t)bh * T_ + qb * 128 + row) * PQ_ + g0 * 8;
        const uint32_t sbase = smb + SQ_F + (uint32_t)(row * AT_STR) + g0 * 16;
        #pragma unroll
        for (int g = 0; g < 4; g++)
            CP_ASYNC16(sbase + g * 16, (const char*)(qf + gbase + g * 8));
        CP_COMMIT();
    }

    const int srow = tid >> 2;
    const int sg   = (tid & 3) * 2;

    auto load_stage = [&](int kt, int stg) {
        const uint32_t sb = smb + AST_BASE + stg * AST_SIZE;
        const uint32_t so = (uint32_t)(srow * AT_STR + sg * 16);
        const size_t gk = ((size_t)bh * T_ + kt * 64 + srow) * PQ_ + sg * 8;
        const size_t gv = ((size_t)bh * HD_ + srow) * T_ + kt * 64 + sg * 8;
        CP_ASYNC16(sb + AST_K + so,      (const char*)(kf + gk));
        CP_ASYNC16(sb + AST_K + so + 16, (const char*)(kf + gk + 8));
        CP_ASYNC16(sb + AST_V + so,      (const char*)(vf + gv));
        CP_ASYNC16(sb + AST_V + so + 16, (const char*)(vf + gv + 8));
        CP_COMMIT();
    };

    float m0 = -1e30f, m1 = -1e30f, lsum0 = 0.f, lsum1 = 0.f;
    float o[8][4];
    #pragma unroll
    for (int j = 0; j < 8; j++)
        #pragma unroll
        for (int q = 0; q < 4; q++) o[j][q] = 0.f;

    const int lr = lane & 15, lc = lane >> 4;
    const int rowg0 = qb * 128 + wid * 16 + (lane >> 2);
    const int ntiles = 2 * qb + 2;

    load_stage(0, 0);
    load_stage(1, 1);      // ntiles >= 2 always

    int stg = 0;
    for (int kt = 0; kt < ntiles; kt++) {
        if (kt + 2 < ntiles) {
            int ns = stg + 2; if (ns >= 3) ns -= 3;
            load_stage(kt + 2, ns);
            CP_WAIT(2);
        } else if (kt + 1 < ntiles) {
            CP_WAIT(1);
        } else {
            CP_WAIT(0);
        }
        __syncthreads();

        const uint32_t sb = smb + AST_BASE + stg * AST_SIZE;

        float s[8][4];
        #pragma unroll
        for (int j = 0; j < 8; j++)
            #pragma unroll
            for (int q = 0; q < 4; q++) s[j][q] = 0.f;

        #pragma unroll
        for (int ks = 0; ks < 4; ks++) {
            const uint32_t kb = (uint32_t)(lc * 16 + ks * 32);
            uint32_t aq[4];
            uint32_t ao = smb + SQ_F + (uint32_t)((wid * 16 + lr) * AT_STR) + kb;
            LDSM_X4(aq[0], aq[1], aq[2], aq[3], ao);
            #pragma unroll
            for (int np = 0; np < 4; np++) {
                uint32_t bo = sb + AST_K + (uint32_t)((np * 16 + lr) * AT_STR) + kb;
                uint32_t b0, b1, b2, b3;
                LDSM_X4(b0, b1, b2, b3, bo);
                mma16816h(s[np * 2 + 0], aq, b0, b2);
                mma16816h(s[np * 2 + 1], aq, b1, b3);
            }
        }

        if (kt >= 2 * qb) {
            const int colb = kt * 64 + 2 * (lane & 3);
            #pragma unroll
            for (int j = 0; j < 8; j++) {
                int c0 = colb + 8 * j;
                if (c0     > rowg0)     s[j][0] = -1e30f;
                if (c0 + 1 > rowg0)     s[j][1] = -1e30f;
                if (c0     > rowg0 + 8) s[j][2] = -1e30f;
                if (c0 + 1 > rowg0 + 8) s[j][3] = -1e30f;
            }
        }

        float mx0 = -1e30f, mx1 = -1e30f;
        #pragma unroll
        for (int j = 0; j < 8; j++) {
            mx0 = fmaxf(mx0, fmaxf(s[j][0], s[j][1]));
            mx1 = fmaxf(mx1, fmaxf(s[j][2], s[j][3]));
        }
        mx0 = fmaxf(mx0, __shfl_xor_sync(0xffffffffu, mx0, 1));
        mx0 = fmaxf(mx0, __shfl_xor_sync(0xffffffffu, mx0, 2));
        mx1 = fmaxf(mx1, __shfl_xor_sync(0xffffffffu, mx1, 1));
        mx1 = fmaxf(mx1, __shfl_xor_sync(0xffffffffu, mx1, 2));

        float mn0 = fmaxf(m0, mx0), mn1 = fmaxf(m1, mx1);
        float a0 = ex2f(m0 - mn0),  a1 = ex2f(m1 - mn1);
        m0 = mn0; m1 = mn1;

        float sum0 = 0.f, sum1 = 0.f;
        #pragma unroll
        for (int j = 0; j < 8; j++) {
            s[j][0] = ex2f(s[j][0] - mn0);
            s[j][1] = ex2f(s[j][1] - mn0);
            s[j][2] = ex2f(s[j][2] - mn1);
            s[j][3] = ex2f(s[j][3] - mn1);
            sum0 += s[j][0] + s[j][1];
            sum1 += s[j][2] + s[j][3];
        }
        sum0 += __shfl_xor_sync(0xffffffffu, sum0, 1);
        sum0 += __shfl_xor_sync(0xffffffffu, sum0, 2);
        sum1 += __shfl_xor_sync(0xffffffffu, sum1, 1);
        sum1 += __shfl_xor_sync(0xffffffffu, sum1, 2);
        lsum0 = lsum0 * a0 + sum0;
        lsum1 = lsum1 * a1 + sum1;

        #pragma unroll
        for (int j = 0; j < 8; j++) {
            o[j][0] *= a0; o[j][1] *= a0;
            o[j][2] *= a1; o[j][3] *= a1;
        }

        uint32_t pf[4][4];
        #pragma unroll
        for (int s2 = 0; s2 < 4; s2++) {
            pf[s2][0] = pack_f16(s[2*s2  ][0], s[2*s2  ][1]);
            pf[s2][1] = pack_f16(s[2*s2  ][2], s[2*s2  ][3]);
            pf[s2][2] = pack_f16(s[2*s2+1][0], s[2*s2+1][1]);
            pf[s2][3] = pack_f16(s[2*s2+1][2], s[2*s2+1][3]);
        }

        #pragma unroll
        for (int s2 = 0; s2 < 4; s2++) {
            const uint32_t kb = (uint32_t)(lc * 16 + s2 * 32);
            #pragma unroll
            for (int np = 0; np < 4; np++) {
                uint32_t bo = sb + AST_V + (uint32_t)((np * 16 + lr) * AT_STR) + kb;
                uint32_t b0, b1, b2, b3;
                LDSM_X4(b0, b1, b2, b3, bo);
                mma16816h(o[np * 2 + 0], pf[s2], b0, b2);
                mma16816h(o[np * 2 + 1], pf[s2], b1, b3);
            }
        }
        __syncthreads();
        if (++stg == 3) stg = 0;
    }

    float inv0 = 1.f / lsum0, inv1 = 1.f / lsum1;
    const int tok0 = b * T_ + qb * 128 + wid * 16 + (lane >> 2);
    #pragma unroll
    for (int nf = 0; nf < 8; nf++) {
        int d = h * HD_ + nf * 8 + (lane & 3) * 2;
        *(uint32_t*)(yf + (size_t)tok0 * C_ + d)       = pack_f16(o[nf][0] * inv0, o[nf][1] * inv0);
        *(uint32_t*)(yf + (size_t)(tok0 + 8) * C_ + d) = pack_f16(o[nf][2] * inv1, o[nf][3] * inv1);
    }
}

// ---------------------------------------------------------------------------
extern "C" void kernel_launch(void* const* d_in, const int* in_sizes, int n_in,
                              void* d_out, int out_size)
{
    const float* x      = (const float*)d_in[0];
    const float* W_attn = (const float*)d_in[1];
    const float* b_attn = (const float*)d_in[2];
    const float* W_proj = (const float*)d_in[3];
    const float* b_proj = (const float*)d_in[4];
    float* out = (float*)d_out;

    __half *xf, *wtf, *wptf, *yf, *qpf, *kpf, *vtf;
    cudaGetSymbolAddress((void**)&xf,   g_xf);
    cudaGetSymbolAddress((void**)&wtf,  g_wtf);
    cudaGetSymbolAddress((void**)&wptf, g_wptf);
    cudaGetSymbolAddress((void**)&yf,   g_yf);
    cudaGetSymbolAddress((void**)&qpf,  g_qpf);
    cudaGetSymbolAddress((void**)&kpf,  g_kpf);
    cudaGetSymbolAddress((void**)&vtf,  g_vtf);

    cudaFuncSetAttribute(gemm_mma_kernel<0>,
                         cudaFuncAttributeMaxDynamicSharedMemorySize, GEMM_SMEM);
    cudaFuncSetAttribute(gemm_mma_kernel<1>,
                         cudaFuncAttributeMaxDynamicSharedMemorySize, GEMM_SMEM);
    cudaFuncSetAttribute(attn_mma_kernel,
                         cudaFuncAttributeMaxDynamicSharedMemorySize, ATTN_SMEM);

    // 1) all conversions in one launch
    convert_all<<<XB + 96 * 32 + 32 * 32, 256>>>(x, W_attn, W_proj, xf, wtf, wptf);

    // 2) qkv GEMM (R13 config) with fully fused epilogue
    gemm_mma_kernel<1><<<dim3(3 * C_ / 128, M_ / 128), 256, GEMM_SMEM>>>(
        xf, wtf, b_attn, nullptr, qpf, kpf, vtf, M_, 3 * C_, C_);

    // 3) fp16 flash attention (3-stage) -> yf
    attn_mma_kernel<<<dim3(T_ / 128, NH_, B_), 256, ATTN_SMEM>>>(qpf, kpf, vtf, yf);

    // 4) out = y @ W_proj + b_proj
    gemm_mma_kernel<0><<<dim3(C_ / 128, M_ / 128), 256, GEMM_SMEM>>>(
        yf, wptf, b_proj, out, nullptr, nullptr, nullptr, M_, C_, C_);
}

// round 16
// speedup vs baseline: 1.1323x; 1.0036x over previous
#include <cuda_runtime.h>
#include <cuda_bf16.h>
#include <cuda_fp16.h>
#include <cstdint>
#include <math.h>

#define B_  4
#define T_  2048
#define C_  1024
#define NH_ 16
#define HD_ 64
#define M_  (B_*T_)          // 8192 tokens
#define PQ_ 72               // padded row length (144B) for q/k prepack

// ---------------- scratch (static device globals; no runtime alloc) --------
__device__ __align__(256) __half  g_xf  [(size_t)M_ * C_];
__device__ __align__(256) __half  g_wtf [(size_t)3 * C_ * C_];   // W_attn^T fp16 [3C, C]
__device__ __align__(256) __half  g_wptf[(size_t)C_ * C_];       // W_proj^T fp16 [C, C]
__device__ __align__(256) __half  g_yf  [(size_t)M_ * C_];       // attn out fp16
__device__ __align__(256) __half  g_qpf [(size_t)B_*NH_*T_*PQ_];
__device__ __align__(256) __half  g_kpf [(size_t)B_*NH_*T_*PQ_];
__device__ __align__(256) __half  g_vtf [(size_t)B_*NH_*HD_*T_];

// ---------------- helpers ---------------------------------------------------
__device__ __forceinline__ uint32_t smem_u32(const void* p) {
    uint32_t a;
    asm("{ .reg .u64 t; cvta.to.shared.u64 t, %1; cvt.u32.u64 %0, t; }" : "=r"(a) : "l"(p));
    return a;
}

#define LDSM_X4(r0, r1, r2, r3, addr) \
    asm volatile("ldmatrix.sync.aligned.m8n8.x4.shared.b16 {%0,%1,%2,%3}, [%4];" \
        : "=r"(r0), "=r"(r1), "=r"(r2), "=r"(r3) : "r"(addr))

#define CP_ASYNC16(dst, src) \
    asm volatile("cp.async.cg.shared.global [%0], [%1], 16;" :: "r"(dst), "l"(src))
#define CP_COMMIT() asm volatile("cp.async.commit_group;" ::: "memory")
#define CP_WAIT(n)  asm volatile("cp.async.wait_group %0;" :: "n"(n) : "memory")

// fp16 MMA
__device__ __forceinline__ void mma16816h(float* d, const uint32_t* a,
                                          uint32_t b0, uint32_t b1) {
    asm("mma.sync.aligned.m16n8k16.row.col.f32.f16.f16.f32 "
        "{%0,%1,%2,%3}, {%4,%5,%6,%7}, {%8,%9}, {%0,%1,%2,%3};"
        : "+f"(d[0]), "+f"(d[1]), "+f"(d[2]), "+f"(d[3])
        : "r"(a[0]), "r"(a[1]), "r"(a[2]), "r"(a[3]), "r"(b0), "r"(b1));
}

__device__ __forceinline__ uint32_t pack_f16(float a, float b) {
    uint32_t r;
    asm("cvt.rn.f16x2.f32 %0, %1, %2;" : "=r"(r) : "f"(b), "f"(a));  // lo16 = a
    return r;
}

__device__ __forceinline__ float ex2f(float x) {
    float r; asm("ex2.approx.f32 %0, %1;" : "=f"(r) : "f"(x)); return r;
}

// ---------------- merged conversion kernel -----------------------------------
#define XB (M_ * C_ / 1024)

__global__ __launch_bounds__(256)
void convert_all(const float* __restrict__ x, const float* __restrict__ Wa,
                 const float* __restrict__ Wp,
                 __half* __restrict__ xf, __half* __restrict__ wtf,
                 __half* __restrict__ wptf)
{
    __shared__ float t[32][33];
    const int bid = blockIdx.x;
    if (bid < XB) {
        int i = (bid * 256 + threadIdx.x) * 4;
        float4 v = *(const float4*)(x + i);
        *(uint2*)(xf + i) = make_uint2(pack_f16(v.x, v.y), pack_f16(v.z, v.w));
        return;
    }
    const float* W; __half* Tf; int K, N, tb;
    if (bid < XB + 96 * 32) { W = Wa; Tf = wtf;  K = C_; N = 3 * C_; tb = bid - XB; }
    else                    { W = Wp; Tf = wptf; K = C_; N = C_;     tb = bid - XB - 96 * 32; }
    const int nblk = N / 32;
    int n0 = (tb % nblk) * 32, k0 = (tb / nblk) * 32;
    int tx = threadIdx.x & 31, ty = threadIdx.x >> 5;
    #pragma unroll
    for (int i = 0; i < 32; i += 8)
        t[ty + i][tx] = W[(size_t)(k0 + ty + i) * N + n0 + tx];
    __syncthreads();
    #pragma unroll
    for (int i = 0; i < 32; i += 8)
        Tf[(size_t)(n0 + ty + i) * K + k0 + tx] = __float2half_rn(t[tx][ty + i]);
}

// ---------------- single-term fp16 GEMM, 3-stage cp.async pipeline ----------
// C[M,N] = A[M,K] @ B[N,K]^T + bias.  K-chunk 32, ASTR 80 (R13 inner loop).
// MODE 0: fp32 C (proj).
// MODE 1: qkv — q/k cols fused fp16 prepack; v cols transposed fp16 [bh,d,T].
#define ASTR 80
#define GSTG 20480                 // 2 arrays x 128 x 80 per stage
#define SM_A  0
#define SM_B  10240
#define SM_BIAS (3 * GSTG)         // 61440
#define GEMM_SMEM (3 * GSTG + 512)

template<int MODE>
__global__ __launch_bounds__(256, 2)
void gemm_mma_kernel(const __half* __restrict__ Af, const __half* __restrict__ Bf,
                     const float* __restrict__ bias, float* __restrict__ Cout,
                     __half* __restrict__ qf, __half* __restrict__ kfp,
                     __half* __restrict__ vf,
                     int M, int N, int K)
{
    extern __shared__ __align__(16) char sm[];
    float* sbias = (float*)(sm + SM_BIAS);
    const uint32_t smb = smem_u32(sm);

    const int tid  = threadIdx.x;
    const int wid  = tid >> 5;
    const int lane = tid & 31;
    const int mw   = wid & 3;
    const int nw   = wid >> 2;
    const int row0 = blockIdx.y * 128;
    const int col0 = blockIdx.x * 128;

    if (tid < 128) sbias[tid] = bias[col0 + tid];

    float acc[2][8][4];
    #pragma unroll
    for (int i = 0; i < 2; i++)
        #pragma unroll
        for (int j = 0; j < 8; j++)
            #pragma unroll
            for (int q = 0; q < 4; q++) acc[i][j][q] = 0.f;

    const int sr0 = tid >> 2;          // 0..63
    const int ssg = tid & 3;           // 16B granule
    const int lr = lane & 15;
    const int lc = lane >> 4;
    const int NC = K >> 5;             // 32 chunks

    auto load_stage = [&](int kc, int stg) {
        const uint32_t sb = smb + stg * GSTG;
        #pragma unroll
        for (int it = 0; it < 2; it++) {
            int r = sr0 + it * 64;
            uint32_t so = (uint32_t)(r * ASTR + ssg * 16);
            size_t ga = (size_t)(row0 + r) * K + (kc << 5) + ssg * 8;
            size_t gb = (size_t)(col0 + r) * K + (kc << 5) + ssg * 8;
            CP_ASYNC16(sb + SM_A + so, (const char*)(Af + ga));
            CP_ASYNC16(sb + SM_B + so, (const char*)(Bf + gb));
        }
        CP_COMMIT();
    };

    load_stage(0, 0);
    load_stage(1, 1);

    int stg = 0;
    for (int kc = 0; kc < NC; kc++) {
        if (kc + 2 < NC) {
            int ns = stg + 2; if (ns >= 3) ns -= 3;
            load_stage(kc + 2, ns);
            CP_WAIT(2);
        } else if (kc + 1 < NC) {
            CP_WAIT(1);
        } else {
            CP_WAIT(0);
        }
        __syncthreads();

        const uint32_t sb = smb + stg * GSTG;
        #pragma unroll
        for (int ks = 0; ks < 2; ks++) {
            const uint32_t kb = (uint32_t)(lc * 16 + ks * 32);

            uint32_t af[2][4];
            #pragma unroll
            for (int mf = 0; mf < 2; mf++) {
                uint32_t ao = sb + SM_A + (uint32_t)((mw * 32 + mf * 16 + lr) * ASTR) + kb;
                LDSM_X4(af[mf][0], af[mf][1], af[mf][2], af[mf][3], ao);
            }

            #pragma unroll
            for (int np = 0; np < 4; np++) {
                uint32_t bo = sb + SM_B + (uint32_t)((nw * 64 + np * 16 + lr) * ASTR) + kb;
                uint32_t b0, b1, b2, b3;
                LDSM_X4(b0, b1, b2, b3, bo);
                mma16816h(acc[0][np * 2 + 0], af[0], b0, b2);
                mma16816h(acc[0][np * 2 + 1], af[0], b1, b3);
                mma16816h(acc[1][np * 2 + 0], af[1], b0, b2);
                mma16816h(acc[1][np * 2 + 1], af[1], b1, b3);
            }
        }
        __syncthreads();
        if (++stg == 3) stg = 0;
    }

    if (MODE == 1) {
        if (col0 < 2 * C_) {
            // fused q/k prepack epilogue: fp16, q pre-scaled by 0.125*log2(e)
            const bool isk = (col0 >= C_);
            const float sc = isk ? 1.0f : 0.125f * 1.44269504089f;
            __half* dst = isk ? kfp : qf;
            const int h0 = (col0 & (C_ - 1)) >> 6;
            #pragma unroll
            for (int mf = 0; mf < 2; mf++) {
                int r_ = row0 + mw * 32 + mf * 16 + (lane >> 2);
                int bi = r_ >> 11, ti = r_ & (T_ - 1);
                #pragma unroll
                for (int nf = 0; nf < 8; nf++) {
                    int cl = nw * 64 + nf * 8 + (lane & 3) * 2;
                    int head = h0 + (cl >> 6), d = cl & 63;
                    float bb0 = sbias[cl], bb1 = sbias[cl + 1];
                    size_t base = ((size_t)(bi * NH_ + head) * T_ + ti) * PQ_ + d;
                    *(uint32_t*)(dst + base) =
                        pack_f16((acc[mf][nf][0] + bb0) * sc, (acc[mf][nf][1] + bb1) * sc);
                    *(uint32_t*)(dst + base + 8 * PQ_) =
                        pack_f16((acc[mf][nf][2] + bb0) * sc, (acc[mf][nf][3] + bb1) * sc);
                }
            }
        } else {
            // fused v epilogue: write transposed fp16 [bh, d, T]
            const int h0 = (col0 - 2 * C_) >> 6;
            #pragma unroll
            for (int mf = 0; mf < 2; mf++) {
                int r_ = row0 + mw * 32 + mf * 16 + (lane >> 2);
                int bi = r_ >> 11, ti = r_ & (T_ - 1);
                #pragma unroll
                for (int nf = 0; nf < 8; nf++) {
                    int cl = nw * 64 + nf * 8 + (lane & 3) * 2;
                    int head = h0 + (cl >> 6), d = cl & 63;
                    float bb0 = sbias[cl], bb1 = sbias[cl + 1];
                    size_t base = ((size_t)(bi * NH_ + head) * HD_ + d) * T_ + ti;
                    vf[base]          = __float2half_rn(acc[mf][nf][0] + bb0);
                    vf[base + T_]     = __float2half_rn(acc[mf][nf][1] + bb1);
                    vf[base + 8]      = __float2half_rn(acc[mf][nf][2] + bb0);
                    vf[base + T_ + 8] = __float2half_rn(acc[mf][nf][3] + bb1);
                }
            }
        }
    } else {
        #pragma unroll
        for (int mf = 0; mf < 2; mf++) {
            int r_ = row0 + mw * 32 + mf * 16 + (lane >> 2);
            #pragma unroll
            for (int nf = 0; nf < 8; nf++) {
                int cl = nw * 64 + nf * 8 + (lane & 3) * 2;
                float b0 = sbias[cl], b1 = sbias[cl + 1];
                float2 v0 = {acc[mf][nf][0] + b0, acc[mf][nf][1] + b1};
                float2 v1 = {acc[mf][nf][2] + b0, acc[mf][nf][3] + b1};
                *(float2*)(Cout + (size_t)r_ * N + col0 + cl) = v0;
                *(float2*)(Cout + (size_t)(r_ + 8) * N + col0 + cl) = v1;
            }
        }
    }
}

// ---------------- fp16 flash attention, 3-stage cp.async pipeline -----------
#define AT_STR 144
#define SQ_F 0
#define AST_BASE 18432
#define AST_SIZE 18432
#define AST_K 0
#define AST_V 9216
#define ATTN_SMEM (AST_BASE + 3 * AST_SIZE)   // 73728

__global__ __launch_bounds__(256, 2)
void attn_mma_kernel(const __half* __restrict__ qf, const __half* __restrict__ kf,
                     const __half* __restrict__ vf, __half* __restrict__ yf)
{
    extern __shared__ char sm[];
    const uint32_t smb = smem_u32(sm);
    const int tid = threadIdx.x, lane = tid & 31, wid = tid >> 5;
    const int qb = (int)(gridDim.x - 1 - blockIdx.x);
    const int h  = blockIdx.y, b = blockIdx.z;
    const int bh = b * NH_ + h;

    // Q tile (group 0)
    {
        const int row = tid >> 1, g0 = (tid & 1) * 4;
        const size_t gbase = ((size_t)bh * T_ + qb * 128 + row) * PQ_ + g0 * 8;
        const uint32_t sbase = smb + SQ_F + (uint32_t)(row * AT_STR) + g0 * 16;
        #pragma unroll
        for (int g = 0; g < 4; g++)
            CP_ASYNC16(sbase + g * 16, (const char*)(qf + gbase + g * 8));
        CP_COMMIT();
    }

    const int srow = tid >> 2;
    const int sg   = (tid & 3) * 2;

    auto load_stage = [&](int kt, int stg) {
        const uint32_t sb = smb + AST_BASE + stg * AST_SIZE;
        const uint32_t so = (uint32_t)(srow * AT_STR + sg * 16);
        const size_t gk = ((size_t)bh * T_ + kt * 64 + srow) * PQ_ + sg * 8;
        const size_t gv = ((size_t)bh * HD_ + srow) * T_ + kt * 64 + sg * 8;
        CP_ASYNC16(sb + AST_K + so,      (const char*)(kf + gk));
        CP_ASYNC16(sb + AST_K + so + 16, (const char*)(kf + gk + 8));
        CP_ASYNC16(sb + AST_V + so,      (const char*)(vf + gv));
        CP_ASYNC16(sb + AST_V + so + 16, (const char*)(vf + gv + 8));
        CP_COMMIT();
    };

    float m0 = -1e30f, m1 = -1e30f, lsum0 = 0.f, lsum1 = 0.f;
    float o[8][4];
    #pragma unroll
    for (int j = 0; j < 8; j++)
        #pragma unroll
        for (int q = 0; q < 4; q++) o[j][q] = 0.f;

    const int lr = lane & 15, lc = lane >> 4;
    const int rowg0 = qb * 128 + wid * 16 + (lane >> 2);
    const int ntiles = 2 * qb + 2;

    load_stage(0, 0);
    load_stage(1, 1);      // ntiles >= 2 always

    int stg = 0;
    for (int kt = 0; kt < ntiles; kt++) {
        if (kt + 2 < ntiles) {
            int ns = stg + 2; if (ns >= 3) ns -= 3;
            load_stage(kt + 2, ns);
            CP_WAIT(2);
        } else if (kt + 1 < ntiles) {
            CP_WAIT(1);
        } else {
            CP_WAIT(0);
        }
        __syncthreads();

        const uint32_t sb = smb + AST_BASE + stg * AST_SIZE;

        float s[8][4];
        #pragma unroll
        for (int j = 0; j < 8; j++)
            #pragma unroll
            for (int q = 0; q < 4; q++) s[j][q] = 0.f;

        #pragma unroll
        for (int ks = 0; ks < 4; ks++) {
            const uint32_t kb = (uint32_t)(lc * 16 + ks * 32);
            uint32_t aq[4];
            uint32_t ao = smb + SQ_F + (uint32_t)((wid * 16 + lr) * AT_STR) + kb;
            LDSM_X4(aq[0], aq[1], aq[2], aq[3], ao);
            #pragma unroll
            for (int np = 0; np < 4; np++) {
                uint32_t bo = sb + AST_K + (uint32_t)((np * 16 + lr) * AT_STR) + kb;
                uint32_t b0, b1, b2, b3;
                LDSM_X4(b0, b1, b2, b3, bo);
                mma16816h(s[np * 2 + 0], aq, b0, b2);
                mma16816h(s[np * 2 + 1], aq, b1, b3);
            }
        }

        if (kt >= 2 * qb) {
            const int colb = kt * 64 + 2 * (lane & 3);
            #pragma unroll
            for (int j = 0; j < 8; j++) {
                int c0 = colb + 8 * j;
                if (c0     > rowg0)     s[j][0] = -1e30f;
                if (c0 + 1 > rowg0)     s[j][1] = -1e30f;
                if (c0     > rowg0 + 8) s[j][2] = -1e30f;
                if (c0 + 1 > rowg0 + 8) s[j][3] = -1e30f;
            }
        }

        float mx0 = -1e30f, mx1 = -1e30f;
        #pragma unroll
        for (int j = 0; j < 8; j++) {
            mx0 = fmaxf(mx0, fmaxf(s[j][0], s[j][1]));
            mx1 = fmaxf(mx1, fmaxf(s[j][2], s[j][3]));
        }
        mx0 = fmaxf(mx0, __shfl_xor_sync(0xffffffffu, mx0, 1));
        mx0 = fmaxf(mx0, __shfl_xor_sync(0xffffffffu, mx0, 2));
        mx1 = fmaxf(mx1, __shfl_xor_sync(0xffffffffu, mx1, 1));
        mx1 = fmaxf(mx1, __shfl_xor_sync(0xffffffffu, mx1, 2));

        float mn0 = fmaxf(m0, mx0), mn1 = fmaxf(m1, mx1);
        float a0 = ex2f(m0 - mn0),  a1 = ex2f(m1 - mn1);
        m0 = mn0; m1 = mn1;

        float sum0 = 0.f, sum1 = 0.f;
        #pragma unroll
        for (int j = 0; j < 8; j++) {
            s[j][0] = ex2f(s[j][0] - mn0);
            s[j][1] = ex2f(s[j][1] - mn0);
            s[j][2] = ex2f(s[j][2] - mn1);
            s[j][3] = ex2f(s[j][3] - mn1);
            sum0 += s[j][0] + s[j][1];
            sum1 += s[j][2] + s[j][3];
        }
        sum0 += __shfl_xor_sync(0xffffffffu, sum0, 1);
        sum0 += __shfl_xor_sync(0xffffffffu, sum0, 2);
        sum1 += __shfl_xor_sync(0xffffffffu, sum1, 1);
        sum1 += __shfl_xor_sync(0xffffffffu, sum1, 2);
        lsum0 = lsum0 * a0 + sum0;
        lsum1 = lsum1 * a1 + sum1;

        #pragma unroll
        for (int j = 0; j < 8; j++) {
            o[j][0] *= a0; o[j][1] *= a0;
            o[j][2] *= a1; o[j][3] *= a1;
        }

        uint32_t pf[4][4];
        #pragma unroll
        for (int s2 = 0; s2 < 4; s2++) {
            pf[s2][0] = pack_f16(s[2*s2  ][0], s[2*s2  ][1]);
            pf[s2][1] = pack_f16(s[2*s2  ][2], s[2*s2  ][3]);
            pf[s2][2] = pack_f16(s[2*s2+1][0], s[2*s2+1][1]);
            pf[s2][3] = pack_f16(s[2*s2+1][2], s[2*s2+1][3]);
        }

        #pragma unroll
        for (int s2 = 0; s2 < 4; s2++) {
            const uint32_t kb = (uint32_t)(lc * 16 + s2 * 32);
            #pragma unroll
            for (int np = 0; np < 4; np++) {
                uint32_t bo = sb + AST_V + (uint32_t)((np * 16 + lr) * AT_STR) + kb;
                uint32_t b0, b1, b2, b3;
                LDSM_X4(b0, b1, b2, b3, bo);
                mma16816h(o[np * 2 + 0], pf[s2], b0, b2);
                mma16816h(o[np * 2 + 1], pf[s2], b1, b3);
            }
        }
        __syncthreads();
        if (++stg == 3) stg = 0;
    }

    float inv0 = 1.f / lsum0, inv1 = 1.f / lsum1;
    const int tok0 = b * T_ + qb * 128 + wid * 16 + (lane >> 2);
    #pragma unroll
    for (int nf = 0; nf < 8; nf++) {
        int d = h * HD_ + nf * 8 + (lane & 3) * 2;
        *(uint32_t*)(yf + (size_t)tok0 * C_ + d)       = pack_f16(o[nf][0] * inv0, o[nf][1] * inv0);
        *(uint32_t*)(yf + (size_t)(tok0 + 8) * C_ + d) = pack_f16(o[nf][2] * inv1, o[nf][3] * inv1);
    }
}

// ---------------------------------------------------------------------------
extern "C" void kernel_launch(void* const* d_in, const int* in_sizes, int n_in,
                              void* d_out, int out_size)
{
    const float* x      = (const float*)d_in[0];
    const float* W_attn = (const float*)d_in[1];
    const float* b_attn = (const float*)d_in[2];
    const float* W_proj = (const float*)d_in[3];
    const float* b_proj = (const float*)d_in[4];
    float* out = (float*)d_out;

    __half *xf, *wtf, *wptf, *yf, *qpf, *kpf, *vtf;
    cudaGetSymbolAddress((void**)&xf,   g_xf);
    cudaGetSymbolAddress((void**)&wtf,  g_wtf);
    cudaGetSymbolAddress((void**)&wptf, g_wptf);
    cudaGetSymbolAddress((void**)&yf,   g_yf);
    cudaGetSymbolAddress((void**)&qpf,  g_qpf);
    cudaGetSymbolAddress((void**)&kpf,  g_kpf);
    cudaGetSymbolAddress((void**)&vtf,  g_vtf);

    cudaFuncSetAttribute(gemm_mma_kernel<0>,
                         cudaFuncAttributeMaxDynamicSharedMemorySize, GEMM_SMEM);
    cudaFuncSetAttribute(gemm_mma_kernel<1>,
                         cudaFuncAttributeMaxDynamicSharedMemorySize, GEMM_SMEM);
    cudaFuncSetAttribute(attn_mma_kernel,
                         cudaFuncAttributeMaxDynamicSharedMemorySize, ATTN_SMEM);

    // 1) all conversions in one launch
    convert_all<<<XB + 96 * 32 + 32 * 32, 256>>>(x, W_attn, W_proj, xf, wtf, wptf);

    // 2) qkv GEMM (3-stage pipeline) with fully fused epilogue
    gemm_mma_kernel<1><<<dim3(3 * C_ / 128, M_ / 128), 256, GEMM_SMEM>>>(
        xf, wtf, b_attn, nullptr, qpf, kpf, vtf, M_, 3 * C_, C_);

    // 3) fp16 flash attention (3-stage) -> yf
    attn_mma_kernel<<<dim3(T_ / 128, NH_, B_), 256, ATTN_SMEM>>>(qpf, kpf, vtf, yf);

    // 4) out = y @ W_proj + b_proj (3-stage pipeline)
    gemm_mma_kernel<0><<<dim3(C_ / 128, M_ / 128), 256, GEMM_SMEM>>>(
        yf, wptf, b_proj, out, nullptr, nullptr, nullptr, M_, C_, C_);
}

// round 17
// speedup vs baseline: 1.1529x; 1.0182x over previous
#include <cuda_runtime.h>
#include <cuda_bf16.h>
#include <cuda_fp16.h>
#include <cstdint>
#include <math.h>

#define B_  4
#define T_  2048
#define C_  1024
#define NH_ 16
#define HD_ 64
#define M_  (B_*T_)          // 8192 tokens
#define PQ_ 72               // padded row length (144B) for q/k prepack

// ---------------- scratch (static device globals; no runtime alloc) --------
__device__ __align__(256) __half  g_xf  [(size_t)M_ * C_];
__device__ __align__(256) __half  g_wtf [(size_t)3 * C_ * C_];   // W_attn^T fp16 [3C, C]
__device__ __align__(256) __half  g_wptf[(size_t)C_ * C_];       // W_proj^T fp16 [C, C]
__device__ __align__(256) __half  g_yf  [(size_t)M_ * C_];       // attn out fp16
__device__ __align__(256) __half  g_qpf [(size_t)B_*NH_*T_*PQ_];
__device__ __align__(256) __half  g_kpf [(size_t)B_*NH_*T_*PQ_];
__device__ __align__(256) __half  g_vtf [(size_t)B_*NH_*HD_*T_];

// ---------------- helpers ---------------------------------------------------
__device__ __forceinline__ uint32_t smem_u32(const void* p) {
    uint32_t a;
    asm("{ .reg .u64 t; cvta.to.shared.u64 t, %1; cvt.u32.u64 %0, t; }" : "=r"(a) : "l"(p));
    return a;
}

#define LDSM_X4(r0, r1, r2, r3, addr) \
    asm volatile("ldmatrix.sync.aligned.m8n8.x4.shared.b16 {%0,%1,%2,%3}, [%4];" \
        : "=r"(r0), "=r"(r1), "=r"(r2), "=r"(r3) : "r"(addr))

#define CP_ASYNC16(dst, src) \
    asm volatile("cp.async.cg.shared.global [%0], [%1], 16;" :: "r"(dst), "l"(src))
#define CP_COMMIT() asm volatile("cp.async.commit_group;" ::: "memory")
#define CP_WAIT(n)  asm volatile("cp.async.wait_group %0;" :: "n"(n) : "memory")

// fp16 MMA
__device__ __forceinline__ void mma16816h(float* d, const uint32_t* a,
                                          uint32_t b0, uint32_t b1) {
    asm("mma.sync.aligned.m16n8k16.row.col.f32.f16.f16.f32 "
        "{%0,%1,%2,%3}, {%4,%5,%6,%7}, {%8,%9}, {%0,%1,%2,%3};"
        : "+f"(d[0]), "+f"(d[1]), "+f"(d[2]), "+f"(d[3])
        : "r"(a[0]), "r"(a[1]), "r"(a[2]), "r"(a[3]), "r"(b0), "r"(b1));
}

__device__ __forceinline__ uint32_t pack_f16(float a, float b) {
    uint32_t r;
    asm("cvt.rn.f16x2.f32 %0, %1, %2;" : "=r"(r) : "f"(b), "f"(a));  // lo16 = a
    return r;
}

__device__ __forceinline__ float ex2f(float x) {
    float r; asm("ex2.approx.f32 %0, %1;" : "=f"(r) : "f"(x)); return r;
}

// dual-lane half2 exp2 (MUFU)
__device__ __forceinline__ uint32_t ex2h2(uint32_t x) {
    uint32_t r; asm("ex2.approx.f16x2 %0, %1;" : "=r"(r) : "r"(x)); return r;
}

// ---------------- merged conversion kernel -----------------------------------
#define XB (M_ * C_ / 1024)

__global__ __launch_bounds__(256)
void convert_all(const float* __restrict__ x, const float* __restrict__ Wa,
                 const float* __restrict__ Wp,
                 __half* __restrict__ xf, __half* __restrict__ wtf,
                 __half* __restrict__ wptf)
{
    __shared__ float t[32][33];
    const int bid = blockIdx.x;
    if (bid < XB) {
        int i = (bid * 256 + threadIdx.x) * 4;
        float4 v = *(const float4*)(x + i);
        *(uint2*)(xf + i) = make_uint2(pack_f16(v.x, v.y), pack_f16(v.z, v.w));
        return;
    }
    const float* W; __half* Tf; int K, N, tb;
    if (bid < XB + 96 * 32) { W = Wa; Tf = wtf;  K = C_; N = 3 * C_; tb = bid - XB; }
    else                    { W = Wp; Tf = wptf; K = C_; N = C_;     tb = bid - XB - 96 * 32; }
    const int nblk = N / 32;
    int n0 = (tb % nblk) * 32, k0 = (tb / nblk) * 32;
    int tx = threadIdx.x & 31, ty = threadIdx.x >> 5;
    #pragma unroll
    for (int i = 0; i < 32; i += 8)
        t[ty + i][tx] = W[(size_t)(k0 + ty + i) * N + n0 + tx];
    __syncthreads();
    #pragma unroll
    for (int i = 0; i < 32; i += 8)
        Tf[(size_t)(n0 + ty + i) * K + k0 + tx] = __float2half_rn(t[tx][ty + i]);
}

// ---------------- single-term fp16 GEMM, 3-stage cp.async pipeline ----------
#define ASTR 80
#define GSTG 20480
#define SM_A  0
#define SM_B  10240
#define SM_BIAS (3 * GSTG)
#define GEMM_SMEM (3 * GSTG + 512)

template<int MODE>
__global__ __launch_bounds__(256, 2)
void gemm_mma_kernel(const __half* __restrict__ Af, const __half* __restrict__ Bf,
                     const float* __restrict__ bias, float* __restrict__ Cout,
                     __half* __restrict__ qf, __half* __restrict__ kfp,
                     __half* __restrict__ vf,
                     int M, int N, int K)
{
    extern __shared__ __align__(16) char sm[];
    float* sbias = (float*)(sm + SM_BIAS);
    const uint32_t smb = smem_u32(sm);

    const int tid  = threadIdx.x;
    const int wid  = tid >> 5;
    const int lane = tid & 31;
    const int mw   = wid & 3;
    const int nw   = wid >> 2;
    const int row0 = blockIdx.y * 128;
    const int col0 = blockIdx.x * 128;

    if (tid < 128) sbias[tid] = bias[col0 + tid];

    float acc[2][8][4];
    #pragma unroll
    for (int i = 0; i < 2; i++)
        #pragma unroll
        for (int j = 0; j < 8; j++)
            #pragma unroll
            for (int q = 0; q < 4; q++) acc[i][j][q] = 0.f;

    const int sr0 = tid >> 2;
    const int ssg = tid & 3;
    const int lr = lane & 15;
    const int lc = lane >> 4;
    const int NC = K >> 5;

    auto load_stage = [&](int kc, int stg) {
        const uint32_t sb = smb + stg * GSTG;
        #pragma unroll
        for (int it = 0; it < 2; it++) {
            int r = sr0 + it * 64;
            uint32_t so = (uint32_t)(r * ASTR + ssg * 16);
            size_t ga = (size_t)(row0 + r) * K + (kc << 5) + ssg * 8;
            size_t gb = (size_t)(col0 + r) * K + (kc << 5) + ssg * 8;
            CP_ASYNC16(sb + SM_A + so, (const char*)(Af + ga));
            CP_ASYNC16(sb + SM_B + so, (const char*)(Bf + gb));
        }
        CP_COMMIT();
    };

    load_stage(0, 0);
    load_stage(1, 1);

    int stg = 0;
    for (int kc = 0; kc < NC; kc++) {
        if (kc + 2 < NC) {
            int ns = stg + 2; if (ns >= 3) ns -= 3;
            load_stage(kc + 2, ns);
            CP_WAIT(2);
        } else if (kc + 1 < NC) {
            CP_WAIT(1);
        } else {
            CP_WAIT(0);
        }
        __syncthreads();

        const uint32_t sb = smb + stg * GSTG;
        #pragma unroll
        for (int ks = 0; ks < 2; ks++) {
            const uint32_t kb = (uint32_t)(lc * 16 + ks * 32);

            uint32_t af[2][4];
            #pragma unroll
            for (int mf = 0; mf < 2; mf++) {
                uint32_t ao = sb + SM_A + (uint32_t)((mw * 32 + mf * 16 + lr) * ASTR) + kb;
                LDSM_X4(af[mf][0], af[mf][1], af[mf][2], af[mf][3], ao);
            }

            #pragma unroll
            for (int np = 0; np < 4; np++) {
                uint32_t bo = sb + SM_B + (uint32_t)((nw * 64 + np * 16 + lr) * ASTR) + kb;
                uint32_t b0, b1, b2, b3;
                LDSM_X4(b0, b1, b2, b3, bo);
                mma16816h(acc[0][np * 2 + 0], af[0], b0, b2);
                mma16816h(acc[0][np * 2 + 1], af[0], b1, b3);
                mma16816h(acc[1][np * 2 + 0], af[1], b0, b2);
                mma16816h(acc[1][np * 2 + 1], af[1], b1, b3);
            }
        }
        __syncthreads();
        if (++stg == 3) stg = 0;
    }

    if (MODE == 1) {
        if (col0 < 2 * C_) {
            const bool isk = (col0 >= C_);
            const float sc = isk ? 1.0f : 0.125f * 1.44269504089f;
            __half* dst = isk ? kfp : qf;
            const int h0 = (col0 & (C_ - 1)) >> 6;
            #pragma unroll
            for (int mf = 0; mf < 2; mf++) {
                int r_ = row0 + mw * 32 + mf * 16 + (lane >> 2);
                int bi = r_ >> 11, ti = r_ & (T_ - 1);
                #pragma unroll
                for (int nf = 0; nf < 8; nf++) {
                    int cl = nw * 64 + nf * 8 + (lane & 3) * 2;
                    int head = h0 + (cl >> 6), d = cl & 63;
                    float bb0 = sbias[cl], bb1 = sbias[cl + 1];
                    size_t base = ((size_t)(bi * NH_ + head) * T_ + ti) * PQ_ + d;
                    *(uint32_t*)(dst + base) =
                        pack_f16((acc[mf][nf][0] + bb0) * sc, (acc[mf][nf][1] + bb1) * sc);
                    *(uint32_t*)(dst + base + 8 * PQ_) =
                        pack_f16((acc[mf][nf][2] + bb0) * sc, (acc[mf][nf][3] + bb1) * sc);
                }
            }
        } else {
            const int h0 = (col0 - 2 * C_) >> 6;
            #pragma unroll
            for (int mf = 0; mf < 2; mf++) {
                int r_ = row0 + mw * 32 + mf * 16 + (lane >> 2);
                int bi = r_ >> 11, ti = r_ & (T_ - 1);
                #pragma unroll
                for (int nf = 0; nf < 8; nf++) {
                    int cl = nw * 64 + nf * 8 + (lane & 3) * 2;
                    int head = h0 + (cl >> 6), d = cl & 63;
                    float bb0 = sbias[cl], bb1 = sbias[cl + 1];
                    size_t base = ((size_t)(bi * NH_ + head) * HD_ + d) * T_ + ti;
                    vf[base]          = __float2half_rn(acc[mf][nf][0] + bb0);
                    vf[base + T_]     = __float2half_rn(acc[mf][nf][1] + bb1);
                    vf[base + 8]      = __float2half_rn(acc[mf][nf][2] + bb0);
                    vf[base + T_ + 8] = __float2half_rn(acc[mf][nf][3] + bb1);
                }
            }
        }
    } else {
        #pragma unroll
        for (int mf = 0; mf < 2; mf++) {
            int r_ = row0 + mw * 32 + mf * 16 + (lane >> 2);
            #pragma unroll
            for (int nf = 0; nf < 8; nf++) {
                int cl = nw * 64 + nf * 8 + (lane & 3) * 2;
                float b0 = sbias[cl], b1 = sbias[cl + 1];
                float2 v0 = {acc[mf][nf][0] + b0, acc[mf][nf][1] + b1};
                float2 v1 = {acc[mf][nf][2] + b0, acc[mf][nf][3] + b1};
                *(float2*)(Cout + (size_t)r_ * N + col0 + cl) = v0;
                *(float2*)(Cout + (size_t)(r_ + 8) * N + col0 + cl) = v1;
            }
        }
    }
}

// ---------------- fp16 flash attention, 3-stage, thin softmax ---------------
#define AT_STR 144
#define SQ_F 0
#define AST_BASE 18432
#define AST_SIZE 18432
#define AST_K 0
#define AST_V 9216
#define ATTN_SMEM (AST_BASE + 3 * AST_SIZE)   // 73728

__global__ __launch_bounds__(256, 2)
void attn_mma_kernel(const __half* __restrict__ qf, const __half* __restrict__ kf,
                     const __half* __restrict__ vf, __half* __restrict__ yf)
{
    extern __shared__ char sm[];
    const uint32_t smb = smem_u32(sm);
    const int tid = threadIdx.x, lane = tid & 31, wid = tid >> 5;
    const int qb = (int)(gridDim.x - 1 - blockIdx.x);
    const int h  = blockIdx.y, b = blockIdx.z;
    const int bh = b * NH_ + h;

    // Q tile (group 0)
    {
        const int row = tid >> 1, g0 = (tid & 1) * 4;
        const size_t gbase = ((size_t)bh * T_ + qb * 128 + row) * PQ_ + g0 * 8;
        const uint32_t sbase = smb + SQ_F + (uint32_t)(row * AT_STR) + g0 * 16;
        #pragma unroll
        for (int g = 0; g < 4; g++)
            CP_ASYNC16(sbase + g * 16, (const char*)(qf + gbase + g * 8));
        CP_COMMIT();
    }

    const int srow = tid >> 2;
    const int sg   = (tid & 3) * 2;

    auto load_stage = [&](int kt, int stg) {
        const uint32_t sb = smb + AST_BASE + stg * AST_SIZE;
        const uint32_t so = (uint32_t)(srow * AT_STR + sg * 16);
        const size_t gk = ((size_t)bh * T_ + kt * 64 + srow) * PQ_ + sg * 8;
        const size_t gv = ((size_t)bh * HD_ + srow) * T_ + kt * 64 + sg * 8;
        CP_ASYNC16(sb + AST_K + so,      (const char*)(kf + gk));
        CP_ASYNC16(sb + AST_K + so + 16, (const char*)(kf + gk + 8));
        CP_ASYNC16(sb + AST_V + so,      (const char*)(vf + gv));
        CP_ASYNC16(sb + AST_V + so + 16, (const char*)(vf + gv + 8));
        CP_COMMIT();
    };

    float m0 = -1e30f, m1 = -1e30f, lsum0 = 0.f, lsum1 = 0.f;
    float o[8][4];
    #pragma unroll
    for (int j = 0; j < 8; j++)
        #pragma unroll
        for (int q = 0; q < 4; q++) o[j][q] = 0.f;

    // fp16 ones B-fragment for row-sum MMA: col n=0 -> lanes 0..3
    const uint32_t bones = (lane < 4) ? 0x3C003C00u : 0u;

    const int lr = lane & 15, lc = lane >> 4;
    const int rowg0 = qb * 128 + wid * 16 + (lane >> 2);
    const int ntiles = 2 * qb + 2;

    load_stage(0, 0);
    load_stage(1, 1);      // ntiles >= 2 always

    int stg = 0;
    for (int kt = 0; kt < ntiles; kt++) {
        if (kt + 2 < ntiles) {
            int ns = stg + 2; if (ns >= 3) ns -= 3;
            load_stage(kt + 2, ns);
            CP_WAIT(2);
        } else if (kt + 1 < ntiles) {
            CP_WAIT(1);
        } else {
            CP_WAIT(0);
        }
        __syncthreads();

        const uint32_t sb = smb + AST_BASE + stg * AST_SIZE;

        float s[8][4];
        #pragma unroll
        for (int j = 0; j < 8; j++)
            #pragma unroll
            for (int q = 0; q < 4; q++) s[j][q] = 0.f;

        #pragma unroll
        for (int ks = 0; ks < 4; ks++) {
            const uint32_t kb = (uint32_t)(lc * 16 + ks * 32);
            uint32_t aq[4];
            uint32_t ao = smb + SQ_F + (uint32_t)((wid * 16 + lr) * AT_STR) + kb;
            LDSM_X4(aq[0], aq[1], aq[2], aq[3], ao);
            #pragma unroll
            for (int np = 0; np < 4; np++) {
                uint32_t bo = sb + AST_K + (uint32_t)((np * 16 + lr) * AT_STR) + kb;
                uint32_t b0, b1, b2, b3;
                LDSM_X4(b0, b1, b2, b3, bo);
                mma16816h(s[np * 2 + 0], aq, b0, b2);
                mma16816h(s[np * 2 + 1], aq, b1, b3);
            }
        }

        if (kt >= 2 * qb) {
            const int colb = kt * 64 + 2 * (lane & 3);
            #pragma unroll
            for (int j = 0; j < 8; j++) {
                int c0 = colb + 8 * j;
                if (c0     > rowg0)     s[j][0] = -1e30f;
                if (c0 + 1 > rowg0)     s[j][1] = -1e30f;
                if (c0     > rowg0 + 8) s[j][2] = -1e30f;
                if (c0 + 1 > rowg0 + 8) s[j][3] = -1e30f;
            }
        }

        float mx0 = -1e30f, mx1 = -1e30f;
        #pragma unroll
        for (int j = 0; j < 8; j++) {
            mx0 = fmaxf(mx0, fmaxf(s[j][0], s[j][1]));
            mx1 = fmaxf(mx1, fmaxf(s[j][2], s[j][3]));
        }
        mx0 = fmaxf(mx0, __shfl_xor_sync(0xffffffffu, mx0, 1));
        mx0 = fmaxf(mx0, __shfl_xor_sync(0xffffffffu, mx0, 2));
        mx1 = fmaxf(mx1, __shfl_xor_sync(0xffffffffu, mx1, 1));
        mx1 = fmaxf(mx1, __shfl_xor_sync(0xffffffffu, mx1, 2));

        float mn0 = fmaxf(m0, mx0), mn1 = fmaxf(m1, mx1);
        float a0 = ex2f(m0 - mn0),  a1 = ex2f(m1 - mn1);
        m0 = mn0; m1 = mn1;

        // ---- P = exp2(s - m) via half2 MUFU (result IS the fp16 fragment) ----
        uint32_t pf[4][4];
        #pragma unroll
        for (int s2 = 0; s2 < 4; s2++) {
            pf[s2][0] = ex2h2(pack_f16(s[2*s2  ][0] - mn0, s[2*s2  ][1] - mn0));
            pf[s2][1] = ex2h2(pack_f16(s[2*s2  ][2] - mn1, s[2*s2  ][3] - mn1));
            pf[s2][2] = ex2h2(pack_f16(s[2*s2+1][0] - mn0, s[2*s2+1][1] - mn0));
            pf[s2][3] = ex2h2(pack_f16(s[2*s2+1][2] - mn1, s[2*s2+1][3] - mn1));
        }

        #pragma unroll
        for (int j = 0; j < 8; j++) {
            o[j][0] *= a0; o[j][1] *= a0;
            o[j][2] *= a1; o[j][3] *= a1;
        }

        // ---- row sums via ones-column MMA (fp32 accum from same fp16 P) ----
        float sums[4] = {0.f, 0.f, 0.f, 0.f};
        #pragma unroll
        for (int s2 = 0; s2 < 4; s2++)
            mma16816h(sums, pf[s2], bones, bones);
        lsum0 = lsum0 * a0 + sums[0];   // valid in lanes with (lane&3)==0
        lsum1 = lsum1 * a1 + sums[2];

        // ---- O += P @ V ----
        #pragma unroll
        for (int s2 = 0; s2 < 4; s2++) {
            const uint32_t kb = (uint32_t)(lc * 16 + s2 * 32);
            #pragma unroll
            for (int np = 0; np < 4; np++) {
                uint32_t bo = sb + AST_V + (uint32_t)((np * 16 + lr) * AT_STR) + kb;
                uint32_t b0, b1, b2, b3;
                LDSM_X4(b0, b1, b2, b3, bo);
                mma16816h(o[np * 2 + 0], pf[s2], b0, b2);
                mma16816h(o[np * 2 + 1], pf[s2], b1, b3);
            }
        }
        __syncthreads();
        if (++stg == 3) stg = 0;
    }

    // broadcast quad-leader lsum to all quad lanes
    float ls0 = __shfl_sync(0xffffffffu, lsum0, lane & ~3);
    float ls1 = __shfl_sync(0xffffffffu, lsum1, lane & ~3);
    float inv0 = 1.f / ls0, inv1 = 1.f / ls1;
    const int tok0 = b * T_ + qb * 128 + wid * 16 + (lane >> 2);
    #pragma unroll
    for (int nf = 0; nf < 8; nf++) {
        int d = h * HD_ + nf * 8 + (lane & 3) * 2;
        *(uint32_t*)(yf + (size_t)tok0 * C_ + d)       = pack_f16(o[nf][0] * inv0, o[nf][1] * inv0);
        *(uint32_t*)(yf + (size_t)(tok0 + 8) * C_ + d) = pack_f16(o[nf][2] * inv1, o[nf][3] * inv1);
    }
}

// ---------------------------------------------------------------------------
extern "C" void kernel_launch(void* const* d_in, const int* in_sizes, int n_in,
                              void* d_out, int out_size)
{
    const float* x      = (const float*)d_in[0];
    const float* W_attn = (const float*)d_in[1];
    const float* b_attn = (const float*)d_in[2];
    const float* W_proj = (const float*)d_in[3];
    const float* b_proj = (const float*)d_in[4];
    float* out = (float*)d_out;

    __half *xf, *wtf, *wptf, *yf, *qpf, *kpf, *vtf;
    cudaGetSymbolAddress((void**)&xf,   g_xf);
    cudaGetSymbolAddress((void**)&wtf,  g_wtf);
    cudaGetSymbolAddress((void**)&wptf, g_wptf);
    cudaGetSymbolAddress((void**)&yf,   g_yf);
    cudaGetSymbolAddress((void**)&qpf,  g_qpf);
    cudaGetSymbolAddress((void**)&kpf,  g_kpf);
    cudaGetSymbolAddress((void**)&vtf,  g_vtf);

    cudaFuncSetAttribute(gemm_mma_kernel<0>,
                         cudaFuncAttributeMaxDynamicSharedMemorySize, GEMM_SMEM);
    cudaFuncSetAttribute(gemm_mma_kernel<1>,
                         cudaFuncAttributeMaxDynamicSharedMemorySize, GEMM_SMEM);
    cudaFuncSetAttribute(attn_mma_kernel,
                         cudaFuncAttributeMaxDynamicSharedMemorySize, ATTN_SMEM);

    // 1) all conversions in one launch
    convert_all<<<XB + 96 * 32 + 32 * 32, 256>>>(x, W_attn, W_proj, xf, wtf, wptf);

    // 2) qkv GEMM with fully fused epilogue
    gemm_mma_kernel<1><<<dim3(3 * C_ / 128, M_ / 128), 256, GEMM_SMEM>>>(
        xf, wtf, b_attn, nullptr, qpf, kpf, vtf, M_, 3 * C_, C_);

    // 3) fp16 flash attention (thin softmax) -> yf
    attn_mma_kernel<<<dim3(T_ / 128, NH_, B_), 256, ATTN_SMEM>>>(qpf, kpf, vtf, yf);

    // 4) out = y @ W_proj + b_proj
    gemm_mma_kernel<0><<<dim3(C_ / 128, M_ / 128), 256, GEMM_SMEM>>>(
        yf, wptf, b_proj, out, nullptr, nullptr, nullptr, M_, C_, C_);
}